// round 5
// baseline (speedup 1.0000x reference)
#include <cuda_runtime.h>
#include <cstdint>

#define N_NODES 50000
#define N_EDGES 800000
#define H 64

// ---------------- scratch (device globals; no allocations) ----------------
__device__ __align__(16) float g_x0 [N_NODES * H];
__device__ __align__(16) float g_x  [N_NODES * H];
__device__ __align__(16) float g_abuf[2][N_NODES * H];   // ping-pong: x @ Wa
__device__ __align__(16) float g_bbuf[2][N_NODES * H];   // ping-pong: x @ Wb
__device__ __align__(16) int g_deg[N_NODES];
__device__ int g_off[N_NODES + 1];
__device__ int g_cursor[N_NODES];
__device__ int g_csr[N_EDGES];

// silu(z) = 0.5*z*(1 + tanh(z/2)) -- single MUFU.TANH
__device__ __forceinline__ float silu_f(float z) {
    float t;
    asm("tanh.approx.f32 %0, %1;" : "=f"(t) : "f"(0.5f * z));
    return 0.5f * z * (1.0f + t);
}
__device__ __forceinline__ float4 silu4(float4 z) {
    return make_float4(silu_f(z.x), silu_f(z.y), silu_f(z.z), silu_f(z.w));
}
__device__ __forceinline__ float4 add4(float4 a, float4 b) {
    return make_float4(a.x + b.x, a.y + b.y, a.z + b.z, a.w + b.w);
}

// ============================ CSR construction =============================
__global__ void k_zero_deg() {
    int i = blockIdx.x * blockDim.x + threadIdx.x;
    if (i < N_NODES) g_deg[i] = 0;
}

// 4 edges/thread for MLP on the atomics
__global__ void k_hist(const int* __restrict__ ei) {
    int i = blockIdx.x * blockDim.x + threadIdx.x;
    if (i < N_EDGES / 4) {
        int4 v = ((const int4*)ei)[i];
        atomicAdd(&g_deg[v.x], 1);
        atomicAdd(&g_deg[v.y], 1);
        atomicAdd(&g_deg[v.z], 1);
        atomicAdd(&g_deg[v.w], 1);
    }
}

// single-block scan, 4 elements/thread (13 tiles of 4096)
__global__ __launch_bounds__(1024) void k_scan() {
    __shared__ int wsum[32];
    __shared__ int s_carry;
    const int tid = threadIdx.x, lane = tid & 31, w = tid >> 5;
    if (tid == 0) { g_off[0] = 0; s_carry = 0; }
    __syncthreads();
    const int NI4 = N_NODES / 4;  // 12500
    for (int base = 0; base < NI4; base += 1024) {
        int i4 = base + tid;
        int4 v = make_int4(0, 0, 0, 0);
        if (i4 < NI4) v = ((const int4*)g_deg)[i4];
        int s0 = v.x, s1 = s0 + v.y, s2 = s1 + v.z, s3 = s2 + v.w;
        int x = s3;
        #pragma unroll
        for (int o = 1; o < 32; o <<= 1) {
            int t = __shfl_up_sync(0xFFFFFFFFu, x, o);
            if (lane >= o) x += t;
        }
        if (lane == 31) wsum[w] = x;
        __syncthreads();
        if (w == 0) {
            int ws = wsum[lane];
            #pragma unroll
            for (int o = 1; o < 32; o <<= 1) {
                int t = __shfl_up_sync(0xFFFFFFFFu, ws, o);
                if (lane >= o) ws += t;
            }
            wsum[lane] = ws;
        }
        __syncthreads();
        int c = s_carry;
        int ex = (x - s3) + (w ? wsum[w - 1] : 0) + c;   // exclusive prefix
        int tile_total = wsum[31];
        if (i4 < NI4) {
            int o = i4 * 4;
            g_off[o + 1] = ex + s0;  g_off[o + 2] = ex + s1;
            g_off[o + 3] = ex + s2;  g_off[o + 4] = ex + s3;
            g_cursor[o] = ex;            g_cursor[o + 1] = ex + s0;
            g_cursor[o + 2] = ex + s1;   g_cursor[o + 3] = ex + s2;
        }
        __syncthreads();
        if (tid == 0) s_carry = c + tile_total;
        __syncthreads();
    }
}

// 4 edges/thread
__global__ void k_scatter(const int* __restrict__ ei) {
    int i = blockIdx.x * blockDim.x + threadIdx.x;
    if (i < N_EDGES / 4) {
        int4 s = ((const int4*)ei)[i];
        int4 d = ((const int4*)(ei + N_EDGES))[i];
        int p0 = atomicAdd(&g_cursor[s.x], 1);
        int p1 = atomicAdd(&g_cursor[s.y], 1);
        int p2 = atomicAdd(&g_cursor[s.z], 1);
        int p3 = atomicAdd(&g_cursor[s.w], 1);
        g_csr[p0] = d.x; g_csr[p1] = d.y; g_csr[p2] = d.z; g_csr[p3] = d.w;
    }
}

// ====================== fused embed + interact-GEMM(0) =====================
__global__ __launch_bounds__(640) void k_embed_ab(
    const float* __restrict__ oh, const float* __restrict__ pos,
    const float* __restrict__ embW, const float* __restrict__ embB,
    const float* __restrict__ Wab0) {
    extern __shared__ float smem[];
    float* Ws   = smem;               // 7744
    float* Wab  = smem + 7744;        // 8192
    float* in_s = smem + 7744 + 8192; // 4840
    float* xs   = in_s + 4840;        // 2560
    const int tid = threadIdx.x;
    const int node0 = blockIdx.x * 40;
    {
        float4* d = (float4*)Ws; const float4* s = (const float4*)embW;
        for (int i = tid; i < 7744 / 4; i += 640) d[i] = s[i];
        float4* d2 = (float4*)Wab; const float4* s2 = (const float4*)Wab0;
        for (int i = tid; i < 8192 / 4; i += 640) d2[i] = s2[i];
    }
    for (int i = tid; i < 40 * 118; i += 640) {
        int row = i / 118, k = i % 118;
        in_s[row * 121 + k] = oh[(size_t)(node0 + row) * 118 + k];
    }
    for (int i = tid; i < 40 * 3; i += 640) {
        int row = i / 3, k = i % 3;
        in_s[row * 121 + 118 + k] = pos[(size_t)(node0 + row) * 3 + k];
    }
    __syncthreads();
    const int r = tid >> 4, cg = tid & 15;
    const int node = node0 + r;
    const float4* Ws4 = (const float4*)Ws;
    float4 acc = __ldg((const float4*)(embB) + cg);
    #pragma unroll 8
    for (int k = 0; k < 121; k++) {
        float h = in_s[r * 121 + k];
        float4 w = Ws4[k * 16 + cg];
        acc.x = fmaf(h, w.x, acc.x); acc.y = fmaf(h, w.y, acc.y);
        acc.z = fmaf(h, w.z, acc.z); acc.w = fmaf(h, w.w, acc.w);
    }
    float4 xv = silu4(acc);
    *(float4*)(g_x0 + (size_t)node * 64 + cg * 4) = xv;
    *(float4*)(g_x  + (size_t)node * 64 + cg * 4) = xv;
    ((float4*)xs)[r * 16 + cg] = xv;
    __syncthreads();
    const float4* Wa4 = (const float4*)Wab;
    const float4* Wb4 = Wa4 + 1024;
    float4 a4 = make_float4(0, 0, 0, 0), b4 = a4;
    #pragma unroll 8
    for (int k = 0; k < 64; k++) {
        float x = xs[r * 64 + k];
        float4 wa = Wa4[k * 16 + cg], wb = Wb4[k * 16 + cg];
        a4.x = fmaf(x, wa.x, a4.x); a4.y = fmaf(x, wa.y, a4.y);
        a4.z = fmaf(x, wa.z, a4.z); a4.w = fmaf(x, wa.w, a4.w);
        b4.x = fmaf(x, wb.x, b4.x); b4.y = fmaf(x, wb.y, b4.y);
        b4.z = fmaf(x, wb.z, b4.z); b4.w = fmaf(x, wb.w, b4.w);
    }
    *(float4*)(g_abuf[0] + (size_t)node * 64 + cg * 4) = a4;
    *(float4*)(g_bbuf[0] + (size_t)node * 64 + cg * 4) = b4;
}

// ============= gather phase (device fn shared by layer kernels) ============
// one warp per node; half-warp per edge; unroll 2 -> 4 edges in flight
__device__ __forceinline__ void gather_phase(
    float* sacc, const float* __restrict__ abuf, const float* __restrict__ bbuf,
    const float* __restrict__ ibias, int node0, int tid) {
    const int wid = tid >> 5, lane = tid & 31;
    const int hlf = lane >> 4, c4 = lane & 15;
    const float4 bias4 = __ldg((const float4*)ibias + c4);
    for (int nl = wid; nl < 80; nl += 20) {
        const int s = node0 + nl;
        float4 a4 = add4(*(const float4*)(abuf + (size_t)s * 64 + c4 * 4), bias4);
        const int j0 = g_off[s], end = g_off[s + 1];
        float4 acc = make_float4(0, 0, 0, 0);
        int j = j0 + hlf;
        for (; j + 2 < end; j += 4) {
            int d0 = __ldg(g_csr + j);
            int d1 = __ldg(g_csr + j + 2);
            float4 b0 = *(const float4*)(bbuf + (size_t)d0 * 64 + c4 * 4);
            float4 b1 = *(const float4*)(bbuf + (size_t)d1 * 64 + c4 * 4);
            acc = add4(acc, silu4(add4(a4, b0)));
            acc = add4(acc, silu4(add4(a4, b1)));
        }
        for (; j < end; j += 2) {
            int d = __ldg(g_csr + j);
            float4 b0 = *(const float4*)(bbuf + (size_t)d * 64 + c4 * 4);
            acc = add4(acc, silu4(add4(a4, b0)));
        }
        acc.x += __shfl_xor_sync(0xFFFFFFFFu, acc.x, 16);
        acc.y += __shfl_xor_sync(0xFFFFFFFFu, acc.y, 16);
        acc.z += __shfl_xor_sync(0xFFFFFFFFu, acc.z, 16);
        acc.w += __shfl_xor_sync(0xFFFFFFFFu, acc.w, 16);
        if (hlf == 0) ((float4*)sacc)[nl * 16 + c4] = acc;
    }
}

// ============ fused layer: gather + update-GEMM + next interact ============
// 80 nodes/block, 640 threads.  dyn smem: U[4096]|Wab[8192]|xs[5120]|acc[5120]
__global__ __launch_bounds__(640) void k_layer(
    const float* __restrict__ U, const float* __restrict__ ub,
    const float* __restrict__ Wabn, const float* __restrict__ ibias, int cur) {
    extern __shared__ float smem[];
    float* Us   = smem;
    float* Wab  = smem + 4096;
    float* xs   = smem + 4096 + 8192;
    float* sacc = xs + 5120;
    const int tid = threadIdx.x;
    const int node0 = blockIdx.x * 80;
    const float* abuf = g_abuf[cur];
    const float* bbuf = g_bbuf[cur];
    float* anx = g_abuf[cur ^ 1];
    float* bnx = g_bbuf[cur ^ 1];
    // smem fills (overlap with gather)
    {
        float4* d = (float4*)Us; const float4* s = (const float4*)U;
        for (int i = tid; i < 1024; i += 640) d[i] = s[i];
        float4* d2 = (float4*)Wab; const float4* s2 = (const float4*)Wabn;
        for (int i = tid; i < 2048; i += 640) d2[i] = s2[i];
        for (int i = tid; i < 1280; i += 640) {
            int row = i >> 4, c4 = i & 15;
            ((float4*)xs)[i] = *(const float4*)(g_x + (size_t)(node0 + row) * 64 + c4 * 4);
        }
    }
    gather_phase(sacc, abuf, bbuf, ibias, node0, tid);
    __syncthreads();
    // hs = x + 0.25*acc (in place over sacc)
    for (int i = tid; i < 1280; i += 640) {
        float4 xv = ((float4*)xs)[i];
        float4 av = ((float4*)sacc)[i];
        ((float4*)sacc)[i] = make_float4(xv.x + 0.25f * av.x, xv.y + 0.25f * av.y,
                                         xv.z + 0.25f * av.z, xv.w + 0.25f * av.w);
    }
    __syncthreads();
    const int rl = tid >> 4, cg = tid & 15;
    const float4* Us4 = (const float4*)Us;
    float4 bias4 = __ldg((const float4*)(ub) + cg);
    float4 acc0 = bias4, acc1 = bias4;
    #pragma unroll 8
    for (int k = 0; k < 64; k++) {
        float4 w = Us4[k * 16 + cg];
        float h0 = sacc[rl * 64 + k];
        float h1 = sacc[(rl + 40) * 64 + k];
        acc0.x = fmaf(h0, w.x, acc0.x); acc0.y = fmaf(h0, w.y, acc0.y);
        acc0.z = fmaf(h0, w.z, acc0.z); acc0.w = fmaf(h0, w.w, acc0.w);
        acc1.x = fmaf(h1, w.x, acc1.x); acc1.y = fmaf(h1, w.y, acc1.y);
        acc1.z = fmaf(h1, w.z, acc1.z); acc1.w = fmaf(h1, w.w, acc1.w);
    }
    float4 sv0 = silu4(acc0), sv1 = silu4(acc1);
    float4 xo0 = ((float4*)xs)[rl * 16 + cg];
    float4 xo1 = ((float4*)xs)[(rl + 40) * 16 + cg];
    float4 xn0 = add4(xo0, sv0), xn1 = add4(xo1, sv1);
    *(float4*)(g_x + (size_t)(node0 + rl) * 64 + cg * 4) = xn0;
    *(float4*)(g_x + (size_t)(node0 + rl + 40) * 64 + cg * 4) = xn1;
    ((float4*)xs)[rl * 16 + cg] = xn0;
    ((float4*)xs)[(rl + 40) * 16 + cg] = xn1;
    __syncthreads();
    const float4* Wa4 = (const float4*)Wab;
    const float4* Wb4 = Wa4 + 1024;
    float4 a0 = make_float4(0, 0, 0, 0), b0 = a0, a1 = a0, b1 = a0;
    #pragma unroll 4
    for (int k = 0; k < 64; k++) {
        float4 wa = Wa4[k * 16 + cg], wb = Wb4[k * 16 + cg];
        float x0 = xs[rl * 64 + k];
        float x1 = xs[(rl + 40) * 64 + k];
        a0.x = fmaf(x0, wa.x, a0.x); a0.y = fmaf(x0, wa.y, a0.y);
        a0.z = fmaf(x0, wa.z, a0.z); a0.w = fmaf(x0, wa.w, a0.w);
        b0.x = fmaf(x0, wb.x, b0.x); b0.y = fmaf(x0, wb.y, b0.y);
        b0.z = fmaf(x0, wb.z, b0.z); b0.w = fmaf(x0, wb.w, b0.w);
        a1.x = fmaf(x1, wa.x, a1.x); a1.y = fmaf(x1, wa.y, a1.y);
        a1.z = fmaf(x1, wa.z, a1.z); a1.w = fmaf(x1, wa.w, a1.w);
        b1.x = fmaf(x1, wb.x, b1.x); b1.y = fmaf(x1, wb.y, b1.y);
        b1.z = fmaf(x1, wb.z, b1.z); b1.w = fmaf(x1, wb.w, b1.w);
    }
    *(float4*)(anx + (size_t)(node0 + rl) * 64 + cg * 4) = a0;
    *(float4*)(bnx + (size_t)(node0 + rl) * 64 + cg * 4) = b0;
    *(float4*)(anx + (size_t)(node0 + rl + 40) * 64 + cg * 4) = a1;
    *(float4*)(bnx + (size_t)(node0 + rl + 40) * 64 + cg * 4) = b1;
}

// ============== fused last layer: gather + update + output head ============
// dyn smem: U[4096] | xs[5120] | acc[5120] | Wos[192+pad]
__global__ __launch_bounds__(640) void k_layer_out(
    const float* __restrict__ U, const float* __restrict__ ub,
    const float* __restrict__ ibias,
    const float* __restrict__ Wo, const float* __restrict__ bo,
    float* __restrict__ out, int cur) {
    extern __shared__ float smem[];
    float* Us   = smem;
    float* xs   = smem + 4096;
    float* sacc = xs + 5120;
    float* Wos  = sacc + 5120;
    const int tid = threadIdx.x;
    const int node0 = blockIdx.x * 80;
    const float* abuf = g_abuf[cur];
    const float* bbuf = g_bbuf[cur];
    {
        float4* d = (float4*)Us; const float4* s = (const float4*)U;
        for (int i = tid; i < 1024; i += 640) d[i] = s[i];
        if (tid < 192) Wos[tid] = Wo[tid];
        for (int i = tid; i < 1280; i += 640) {
            int row = i >> 4, c4 = i & 15;
            ((float4*)xs)[i] = *(const float4*)(g_x + (size_t)(node0 + row) * 64 + c4 * 4);
        }
    }
    gather_phase(sacc, abuf, bbuf, ibias, node0, tid);
    __syncthreads();
    for (int i = tid; i < 1280; i += 640) {
        float4 xv = ((float4*)xs)[i];
        float4 av = ((float4*)sacc)[i];
        ((float4*)sacc)[i] = make_float4(xv.x + 0.25f * av.x, xv.y + 0.25f * av.y,
                                         xv.z + 0.25f * av.z, xv.w + 0.25f * av.w);
    }
    __syncthreads();
    const int rl = tid >> 4, cg = tid & 15;
    const float4* Us4 = (const float4*)Us;
    float4 bias4 = __ldg((const float4*)(ub) + cg);
    float4 acc0 = bias4, acc1 = bias4;
    #pragma unroll 8
    for (int k = 0; k < 64; k++) {
        float4 w = Us4[k * 16 + cg];
        float h0 = sacc[rl * 64 + k];
        float h1 = sacc[(rl + 40) * 64 + k];
        acc0.x = fmaf(h0, w.x, acc0.x); acc0.y = fmaf(h0, w.y, acc0.y);
        acc0.z = fmaf(h0, w.z, acc0.z); acc0.w = fmaf(h0, w.w, acc0.w);
        acc1.x = fmaf(h1, w.x, acc1.x); acc1.y = fmaf(h1, w.y, acc1.y);
        acc1.z = fmaf(h1, w.z, acc1.z); acc1.w = fmaf(h1, w.w, acc1.w);
    }
    float4 sv0 = silu4(acc0), sv1 = silu4(acc1);
    #pragma unroll
    for (int rr = 0; rr < 2; rr++) {
        const int node = node0 + rl + rr * 40;
        float4 sv = rr ? sv1 : sv0;
        float4 xo = ((float4*)xs)[(rl + rr * 40) * 16 + cg];
        float4 x0v = *(const float4*)(g_x0 + (size_t)node * 64 + cg * 4);
        float4 v = make_float4(x0v.x + xo.x + sv.x, x0v.y + xo.y + sv.y,
                               x0v.z + xo.z + sv.z, x0v.w + xo.w + sv.w);
        const int cb = cg * 4;
        float p0 = v.x * Wos[(cb + 0) * 3 + 0] + v.y * Wos[(cb + 1) * 3 + 0]
                 + v.z * Wos[(cb + 2) * 3 + 0] + v.w * Wos[(cb + 3) * 3 + 0];
        float p1 = v.x * Wos[(cb + 0) * 3 + 1] + v.y * Wos[(cb + 1) * 3 + 1]
                 + v.z * Wos[(cb + 2) * 3 + 1] + v.w * Wos[(cb + 3) * 3 + 1];
        float p2 = v.x * Wos[(cb + 0) * 3 + 2] + v.y * Wos[(cb + 1) * 3 + 2]
                 + v.z * Wos[(cb + 2) * 3 + 2] + v.w * Wos[(cb + 3) * 3 + 2];
        #pragma unroll
        for (int off = 8; off > 0; off >>= 1) {
            p0 += __shfl_down_sync(0xFFFFFFFFu, p0, off, 16);
            p1 += __shfl_down_sync(0xFFFFFFFFu, p1, off, 16);
            p2 += __shfl_down_sync(0xFFFFFFFFu, p2, off, 16);
        }
        if (cg == 0) {
            out[node * 3 + 0] = p0 + __ldg(bo + 0);
            out[node * 3 + 1] = p1 + __ldg(bo + 1);
            out[node * 3 + 2] = p2 + __ldg(bo + 2);
        }
    }
}

// ================================ launcher =================================
extern "C" void kernel_launch(void* const* d_in, const int* in_sizes, int n_in,
                              void* d_out, int out_size) {
    const float* oh   = (const float*)d_in[0];
    const float* pos  = (const float*)d_in[1];
    const int*   ei   = (const int*)d_in[2];
    const float* embW = (const float*)d_in[3];
    const float* embB = (const float*)d_in[4];
    const float* iW   = (const float*)d_in[5];   // [4, 128, 64]
    const float* iB   = (const float*)d_in[6];   // [4, 64]
    const float* uW   = (const float*)d_in[7];   // [4, 64, 64]
    const float* uB   = (const float*)d_in[8];   // [4, 64]
    const float* oW   = (const float*)d_in[9];   // [64, 3]
    const float* oB   = (const float*)d_in[10];  // [3]
    float* out = (float*)d_out;

    const int EMBED_SMEM = (7744 + 8192 + 4840 + 2560) * 4;          // 93,344 B
    const int LAYER_SMEM = (4096 + 8192 + 5120 + 5120) * 4;          // 90,112 B
    const int LOUT_SMEM  = (4096 + 5120 + 5120 + 256) * 4;           // 58,368 B
    cudaFuncSetAttribute(k_embed_ab, cudaFuncAttributeMaxDynamicSharedMemorySize, EMBED_SMEM);
    cudaFuncSetAttribute(k_layer,    cudaFuncAttributeMaxDynamicSharedMemorySize, LAYER_SMEM);
    cudaFuncSetAttribute(k_layer_out,cudaFuncAttributeMaxDynamicSharedMemorySize, LOUT_SMEM);

    k_zero_deg<<<(N_NODES + 255) / 256, 256>>>();
    k_hist<<<(N_EDGES / 4 + 255) / 256, 256>>>(ei);
    k_scan<<<1, 1024>>>();
    k_scatter<<<(N_EDGES / 4 + 255) / 256, 256>>>(ei);

    k_embed_ab<<<N_NODES / 40, 640, EMBED_SMEM>>>(oh, pos, embW, embB, iW);
    for (int l = 0; l < 3; l++)
        k_layer<<<N_NODES / 80, 640, LAYER_SMEM>>>(
            uW + (size_t)l * 4096, uB + l * 64,
            iW + (size_t)(l + 1) * 8192, iB + l * 64, l & 1);
    k_layer_out<<<N_NODES / 80, 640, LOUT_SMEM>>>(
        uW + (size_t)3 * 4096, uB + 3 * 64, iB + 3 * 64, oW, oB, out, 3 & 1);
}